// round 10
// baseline (speedup 1.0000x reference)
#include <cuda_runtime.h>
#include <cuda_fp16.h>
#include <cstdint>

// AWD-LSTM persistent kernel v6: fp16 m16n8k16 recurrence + atomic-free
// flag barrier + reordered step loop. T=1024, B=64, DIN=512, H=1024.
// Inputs: x[T,B,DIN], h0[B,H], c0[B,H], Wi[4H,DIN], bi[4H], Wh[4H,H], bh[4H],
//         input_tokens[T,B] i32.  Output: [ out(T*B*H) | hT(B*H) | cT(B*H) ].

#define TT 1024
#define BB 64
#define DD 512
#define HH 1024
#define GG 4096
#define GRID 128
#define BH   (BB * HH)
#define TBH  ((size_t)TT * BB * HH)

// g_h: fp16, A-fragment layout for m16n8k16.
// [buf][mb(4)][u(64)][32 lanes][4 words]; tile (mb,u) = rows [16mb,16mb+16) x
// k [16u,16u+16). Element (r,kin): lane=(r&7)*4+((kin>>1)&3),
// frag=((kin>>3)<<1)|(r>>3), half lo/hi = kin&1.
__device__ float    g_xi[(size_t)TT * BB * GG];   // 1.07 GB scratch
__device__ unsigned g_h[2][4 * 64 * 128];         // 2 x 128 KB
__device__ __align__(512) unsigned g_flags[GRID]; // per-block arrival epochs

__device__ __forceinline__ unsigned f2tf32(float f) {
    unsigned r;
    asm("cvt.rna.tf32.f32 %0, %1;" : "=r"(r) : "f"(f));
    return r;
}

// Pack two f32 into one f16x2 word: lo half = x, hi half = y.
__device__ __forceinline__ unsigned f2h2(float x, float y) {
    unsigned r;
    asm("cvt.rn.f16x2.f32 %0, %1, %2;" : "=r"(r) : "f"(y), "f"(x));
    return r;
}

__device__ __forceinline__ void mma_f16(float d[4], const unsigned a[4], const unsigned b[2]) {
    asm volatile(
        "mma.sync.aligned.m16n8k16.row.col.f32.f16.f16.f32 "
        "{%0,%1,%2,%3}, {%4,%5,%6,%7}, {%8,%9}, {%0,%1,%2,%3};\n"
        : "+f"(d[0]), "+f"(d[1]), "+f"(d[2]), "+f"(d[3])
        : "r"(a[0]), "r"(a[1]), "r"(a[2]), "r"(a[3]), "r"(b[0]), "r"(b[1]));
}

__device__ __forceinline__ float sigmf(float x) {
    return __fdividef(1.f, 1.f + __expf(-x));
}
__device__ __forceinline__ float tanhx(float x) {
    return 2.f * sigmf(2.f * x) - 1.f;
}

// ---------------------------------------------------------------------------
// init: g_h[0] = fp16(h0) in fragment layout; clear flags.
// ---------------------------------------------------------------------------
__global__ void init_kernel(const float* __restrict__ h0) {
    int w = blockIdx.x * 256 + threadIdx.x;        // word index, 32768 total
    if (w < 4 * 64 * 128) {
        int mb = w >> 13, u = (w >> 7) & 63;
        int lane = (w >> 2) & 31, frag = w & 3;
        int r = ((frag & 1) << 3) | (lane >> 2);
        int kin = ((frag >> 1) << 3) | ((lane & 3) << 1);
        int b = mb * 16 + r, col = u * 16 + kin;
        float2 v = *(const float2*)(h0 + (size_t)b * HH + col);
        g_h[0][w] = f2h2(v.x, v.y);
    }
    if (blockIdx.x == 0 && threadIdx.x < GRID) g_flags[threadIdx.x] = 0;
}

// ---------------------------------------------------------------------------
// xi = x @ Wi^T + bi, fp16 m16n8k16. M=65536, K=512, N=4096. 64x64 tiles.
// ---------------------------------------------------------------------------
__global__ __launch_bounds__(256) void xi_gemm(const float* __restrict__ x,
                                               const float* __restrict__ Wi,
                                               const float* __restrict__ bi) {
    __shared__ __align__(16) unsigned As2[64][20];   // half2, stride 20
    __shared__ __align__(16) unsigned Bs2[64][20];
    const int n0 = blockIdx.x * 64;
    const int m0 = blockIdx.y * 64;
    const int tid = threadIdx.x;
    const int lane = tid & 31, wid = tid >> 5;
    const int wm = wid >> 2, wn = wid & 3;
    const int g = lane >> 2, tg = lane & 3;

    float acc[2][2][4] = {};

    for (int k0 = 0; k0 < DD; k0 += 32) {
#pragma unroll
        for (int i = 0; i < 2; i++) {
            int f = tid + i * 256;
            int r = f >> 3, kq = (f & 7) << 2, k2 = (f & 7) << 1;
            float4 v = *(const float4*)(x + (size_t)(m0 + r) * DD + k0 + kq);
            As2[r][k2] = f2h2(v.x, v.y);
            As2[r][k2 + 1] = f2h2(v.z, v.w);
            float4 w = *(const float4*)(Wi + (size_t)(n0 + r) * DD + k0 + kq);
            Bs2[r][k2] = f2h2(w.x, w.y);
            Bs2[r][k2 + 1] = f2h2(w.z, w.w);
        }
        __syncthreads();

#pragma unroll
        for (int kk2 = 0; kk2 < 16; kk2 += 8) {
            unsigned a[2][4], bf[2][2];
#pragma unroll
            for (int mi = 0; mi < 2; mi++) {
                int r = wm * 32 + mi * 16;
                a[mi][0] = As2[r + g][kk2 + tg];
                a[mi][1] = As2[r + g + 8][kk2 + tg];
                a[mi][2] = As2[r + g][kk2 + tg + 4];
                a[mi][3] = As2[r + g + 8][kk2 + tg + 4];
            }
#pragma unroll
            for (int ni = 0; ni < 2; ni++) {
                int c = wn * 16 + ni * 8;
                bf[ni][0] = Bs2[c + g][kk2 + tg];
                bf[ni][1] = Bs2[c + g][kk2 + tg + 4];
            }
#pragma unroll
            for (int mi = 0; mi < 2; mi++)
#pragma unroll
                for (int ni = 0; ni < 2; ni++)
                    mma_f16(acc[mi][ni], a[mi], bf[ni]);
        }
        __syncthreads();
    }

#pragma unroll
    for (int mi = 0; mi < 2; mi++)
#pragma unroll
        for (int ni = 0; ni < 2; ni++) {
            int row = m0 + wm * 32 + mi * 16 + g;
            int col = n0 + wn * 16 + ni * 8 + 2 * tg;
            float2 bv = *(const float2*)(bi + col);
            *(float2*)(g_xi + (size_t)row * GG + col) =
                make_float2(acc[mi][ni][0] + bv.x, acc[mi][ni][1] + bv.y);
            *(float2*)(g_xi + (size_t)(row + 8) * GG + col) =
                make_float2(acc[mi][ni][2] + bv.x, acc[mi][ni][3] + bv.y);
        }
}

// ---------------------------------------------------------------------------
// Persistent recurrence. grid=128 x 256thr, 1 CTA/SM.
// Per warp per step: 32 LDG.128 (A) + 32 LDS.128 (B) + 128 HMMA.16816.
// Barrier: per-block flag stores (monotonic epoch) + warp-0 vectorized poll
// (one ld.volatile.v4 per lane covers all 128 flags per round). No atomics.
// ---------------------------------------------------------------------------
__global__ __launch_bounds__(256, 1) void lstm_persist(
    const float* __restrict__ Wh, const float* __restrict__ bh,
    const int* __restrict__ tok, const float* __restrict__ c0,
    float* __restrict__ out, int ne)
{
    extern __shared__ __align__(16) unsigned Bsf[];  // 16384 words = 64 KB
    __shared__ float Ps[64][34];
    __shared__ float Ps2[64][34];

    const int bid = blockIdx.x;
    const int jb = bid * 8;
    const int tid = threadIdx.x, lane = tid & 31, wid = tid >> 5;
    const int ks = wid >> 1, wmh = wid & 1;          // k-quarter, m-half
    const int g = lane >> 2, tg = lane & 3;

    // One-time: Wh -> fp16 fragment-ready smem.
    // [u(64)][ntp(2)][lane(32)][4 words]; see v4b comment for mapping.
#pragma unroll
    for (int i = 0; i < 64; i++) {
        int idx = tid + i * 256;                     // 0..16383
        int u = idx >> 8, rest = idx & 255;
        int ntp = rest >> 7, rr = rest & 127;
        int ln = rr >> 2, w = rr & 3;
        int nt = ntp * 2 + (w >> 1), breg = w & 1;
        int gg = ln >> 2, tt = ln & 3;
        int k = u * 16 + 2 * tt + 8 * breg;
        const float* src = Wh + ((size_t)nt * HH + jb + gg) * HH + k;
        float2 v = *(const float2*)src;
        Bsf[idx] = f2h2(v.x, v.y);
    }

    // Gate-phase mapping: thread -> (b, q), handles j = 2q, 2q+1.
    const int b = tid >> 2, q = tid & 3;
    const int colE = jb + 2 * q;                     // even column
    float2 bhv[4];
#pragma unroll
    for (int gate = 0; gate < 4; gate++)
        bhv[gate] = *(const float2*)(bh + gate * HH + colE);
    float2 creg = *(const float2*)(c0 + (size_t)b * HH + colE);
    float2 hreg = make_float2(0.f, 0.f);

    // h-store word offset in g_h fragment layout (u = bid>>1 fixed).
    unsigned hoff;
    {
        int mb = b >> 4, r = b & 15;
        int kin = 8 * (bid & 1) + 2 * q;
        int ln = (r & 7) * 4 + ((kin >> 1) & 3);
        int frag = ((kin >> 3) << 1) | (r >> 3);
        hoff = ((unsigned)(mb << 6 | (bid >> 1)) << 7) + ln * 4 + frag;
    }
    __syncthreads();

    // Loop-carried xi prefetch for step 0.
    float2 xr[4];
    {
        const float* xb = g_xi + (size_t)b * GG + colE;
#pragma unroll
        for (int gate = 0; gate < 4; gate++)
            xr[gate] = *(const float2*)(xb + gate * HH);
    }

    for (int t = 0; t < TT; t++) {
        // GEMM: preact[64x32] = h[t-1] @ WhTile^T, K=1024, quarter ks.
        const unsigned* gh = g_h[t & 1];
        const uint4* a0p = (const uint4*)gh + ((2 * wmh + 0) * 64 + ks * 16) * 32 + lane;
        const uint4* a1p = (const uint4*)gh + ((2 * wmh + 1) * 64 + ks * 16) * 32 + lane;
        const uint4* bpp = (const uint4*)Bsf + (ks * 16) * 64 + lane;

        float acc[2][4][4] = {};
#pragma unroll 4
        for (int uu = 0; uu < 16; uu++) {
            uint4 A0 = __ldcg(a0p + uu * 32);
            uint4 A1 = __ldcg(a1p + uu * 32);
            uint4 B0 = bpp[uu * 64];
            uint4 B1 = bpp[uu * 64 + 32];
            unsigned af0[4] = { A0.x, A0.y, A0.z, A0.w };
            unsigned af1[4] = { A1.x, A1.y, A1.z, A1.w };
            unsigned b0[2] = { B0.x, B0.y }, b1[2] = { B0.z, B0.w };
            unsigned b2[2] = { B1.x, B1.y }, b3[2] = { B1.z, B1.w };
            mma_f16(acc[0][0], af0, b0); mma_f16(acc[0][1], af0, b1);
            mma_f16(acc[0][2], af0, b2); mma_f16(acc[0][3], af0, b3);
            mma_f16(acc[1][0], af1, b0); mma_f16(acc[1][1], af1, b1);
            mma_f16(acc[1][2], af1, b2); mma_f16(acc[1][3], af1, b3);
        }

        // Reduction: ks0->Ps, ks1->Ps2 (write); ks2->Ps, ks3->Ps2 (add).
        if (ks < 2) {
            float (*P)[34] = (ks == 0) ? Ps : Ps2;
#pragma unroll
            for (int mbi = 0; mbi < 2; mbi++)
#pragma unroll
                for (int nt = 0; nt < 4; nt++) {
                    int r = (2 * wmh + mbi) * 16 + g;
                    int c = nt * 8 + 2 * tg;
                    P[r][c]     = acc[mbi][nt][0];
                    P[r][c + 1] = acc[mbi][nt][1];
                    P[r + 8][c]     = acc[mbi][nt][2];
                    P[r + 8][c + 1] = acc[mbi][nt][3];
                }
        }
        __syncthreads();
        if (ks >= 2) {
            float (*P)[34] = (ks == 2) ? Ps : Ps2;
#pragma unroll
            for (int mbi = 0; mbi < 2; mbi++)
#pragma unroll
                for (int nt = 0; nt < 4; nt++) {
                    int r = (2 * wmh + mbi) * 16 + g;
                    int c = nt * 8 + 2 * tg;
                    P[r][c]     += acc[mbi][nt][0];
                    P[r][c + 1] += acc[mbi][nt][1];
                    P[r + 8][c]     += acc[mbi][nt][2];
                    P[r + 8][c + 1] += acc[mbi][nt][3];
                }
        }
        __syncthreads();

        // Gate phase: 2 outputs (b, colE), (b, colE+1).
        {
            float kc = (t >= 2 && __ldg(tok + (t - 1) * BB + b) == 0) ? 0.f : 1.f;
            float pre[4][2];
#pragma unroll
            for (int gate = 0; gate < 4; gate++) {
                int c = gate * 8 + 2 * q;
                pre[gate][0] = Ps[b][c]     + Ps2[b][c]     + xr[gate].x + bhv[gate].x;
                pre[gate][1] = Ps[b][c + 1] + Ps2[b][c + 1] + xr[gate].y + bhv[gate].y;
            }
            float h2[2], c2[2];
#pragma unroll
            for (int z = 0; z < 2; z++) {
                float iv = sigmf(pre[0][z]);
                float fv = sigmf(pre[1][z]);
                float ov = sigmf(pre[2][z]);
                float gv = tanhx(pre[3][z]);
                float cold = (z == 0 ? creg.x : creg.y) * kc;
                float cn = fv * cold + iv * gv;
                c2[z] = cn;
                h2[z] = ov * tanhx(cn);
            }
            creg = make_float2(c2[0], c2[1]);
            hreg = make_float2(h2[0], h2[1]);
            float kn = ((t + 1) >= 2 && __ldg(tok + t * BB + b) == 0) ? 0.f : 1.f;
            g_h[(t + 1) & 1][hoff] = f2h2(h2[0] * kn, h2[1] * kn);
            *(float2*)(out + (size_t)t * BH + (size_t)b * HH + colE) = hreg;
        }

        // Arrive as early as possible.
        __syncthreads();
        if (tid == 0) {
            __threadfence();
            *(volatile unsigned*)&g_flags[bid] = (unsigned)(t + 1);
        }

        // Prefetch xi for t+1 while waiting (barrier-independent).
        if (t + 1 < TT) {
            const float* xb = g_xi + ((size_t)(t + 1) * BB + b) * GG + colE;
#pragma unroll
            for (int gate = 0; gate < 4; gate++)
                xr[gate] = *(const float2*)(xb + gate * HH);
        }

        // Wait: warp 0 polls all 128 flags, 4 per lane via one v4 load.
        if (tid < 32) {
            unsigned tgt = (unsigned)(t + 1);
            unsigned f0, f1, f2, f3;
            do {
                asm volatile("ld.volatile.global.v4.u32 {%0,%1,%2,%3}, [%4];"
                             : "=r"(f0), "=r"(f1), "=r"(f2), "=r"(f3)
                             : "l"(g_flags + 4 * tid) : "memory");
            } while (f0 < tgt || f1 < tgt || f2 < tgt || f3 < tgt);
            __threadfence();
        }
        __syncthreads();
    }

    // hT / cT tail from registers.
    {
        size_t off = (size_t)b * HH + colE;
        if (ne >= 1) *(float2*)(out + TBH + off) = hreg;
        if (ne >= 2) *(float2*)(out + TBH + BH + off) = creg;
    }
}

extern "C" void kernel_launch(void* const* d_in, const int* in_sizes, int n_in,
                              void* d_out, int out_size) {
    const float* x  = (const float*)d_in[0];
    const float* h0 = (const float*)d_in[1];
    const float* c0 = (const float*)d_in[2];
    const float* Wi = (const float*)d_in[3];
    const float* bi = (const float*)d_in[4];
    const float* Wh = (const float*)d_in[5];
    const float* bh = (const float*)d_in[6];
    const int* tok  = (const int*)d_in[7];
    float* out = (float*)d_out;

    const int dyn_smem = 16384 * 4;  // 64 KB
    cudaFuncSetAttribute(lstm_persist, cudaFuncAttributeMaxDynamicSharedMemorySize, dyn_smem);

    init_kernel<<<(4 * 64 * 128 + 255) / 256, 256>>>(h0);
    xi_gemm<<<dim3(GG / 64, (TT * BB) / 64), 256>>>(x, Wi, bi);

    long long extra = ((long long)out_size - (long long)TBH) / BH;
    int ne = extra < 0 ? 0 : (extra > 2 ? 2 : (int)extra);

    lstm_persist<<<GRID, 256, dyn_smem>>>(Wh, bh, tok, c0, out, ne);
}

// round 13
// speedup vs baseline: 1.3680x; 1.3680x over previous
#include <cuda_runtime.h>
#include <cuda_fp16.h>
#include <cstdint>

// AWD-LSTM persistent kernel v7: v4b + 512-thread blocks (4 warps/SMSP) for
// latency hiding; v4b's proven atomic+epoch barrier restored.
// T=1024, B=64, DIN=512, H=1024.
// Inputs: x[T,B,DIN], h0[B,H], c0[B,H], Wi[4H,DIN], bi[4H], Wh[4H,H], bh[4H],
//         input_tokens[T,B] i32.  Output: [ out(T*B*H) | hT(B*H) | cT(B*H) ].

#define TT 1024
#define BB 64
#define DD 512
#define HH 1024
#define GG 4096
#define GRID 128
#define BH   (BB * HH)
#define TBH  ((size_t)TT * BB * HH)

// g_h: fp16, A-fragment layout for m16n8k16.
// [buf][mb(4)][u(64)][32 lanes][4 words]; tile (mb,u) = rows [16mb,16mb+16) x
// k [16u,16u+16). Element (r,kin): lane=(r&7)*4+((kin>>1)&3),
// frag=((kin>>3)<<1)|(r>>3), half lo/hi = kin&1.
__device__ float    g_xi[(size_t)TT * BB * GG];   // 1.07 GB scratch
__device__ unsigned g_h[2][4 * 64 * 128];         // 2 x 128 KB
__device__ unsigned g_cnt;
__device__ unsigned g_epoch;

__device__ __forceinline__ unsigned f2h2(float x, float y) {
    unsigned r;
    asm("cvt.rn.f16x2.f32 %0, %1, %2;" : "=r"(r) : "f"(y), "f"(x));
    return r;
}

__device__ __forceinline__ void mma_f16(float d[4], const unsigned a[4], const unsigned b[2]) {
    asm volatile(
        "mma.sync.aligned.m16n8k16.row.col.f32.f16.f16.f32 "
        "{%0,%1,%2,%3}, {%4,%5,%6,%7}, {%8,%9}, {%0,%1,%2,%3};\n"
        : "+f"(d[0]), "+f"(d[1]), "+f"(d[2]), "+f"(d[3])
        : "r"(a[0]), "r"(a[1]), "r"(a[2]), "r"(a[3]), "r"(b[0]), "r"(b[1]));
}

__device__ __forceinline__ float sigmf(float x) {
    return __fdividef(1.f, 1.f + __expf(-x));
}
__device__ __forceinline__ float tanhx(float x) {
    return 2.f * sigmf(2.f * x) - 1.f;
}

// ---------------------------------------------------------------------------
// init: g_h[0] = fp16(h0) in fragment layout; reset barrier state.
// ---------------------------------------------------------------------------
__global__ void init_kernel(const float* __restrict__ h0) {
    int w = blockIdx.x * 256 + threadIdx.x;        // word index, 32768 total
    if (w < 4 * 64 * 128) {
        int mb = w >> 13, u = (w >> 7) & 63;
        int lane = (w >> 2) & 31, frag = w & 3;
        int r = ((frag & 1) << 3) | (lane >> 2);
        int kin = ((frag >> 1) << 3) | ((lane & 3) << 1);
        int b = mb * 16 + r, col = u * 16 + kin;
        float2 v = *(const float2*)(h0 + (size_t)b * HH + col);
        g_h[0][w] = f2h2(v.x, v.y);
    }
    if (blockIdx.x == 0 && threadIdx.x == 0) { g_cnt = 0; g_epoch = 0; }
}

// ---------------------------------------------------------------------------
// xi = x @ Wi^T + bi, fp16 m16n8k16. M=65536, K=512, N=4096. 64x64 tiles.
// ---------------------------------------------------------------------------
__global__ __launch_bounds__(256) void xi_gemm(const float* __restrict__ x,
                                               const float* __restrict__ Wi,
                                               const float* __restrict__ bi) {
    __shared__ __align__(16) unsigned As2[64][20];   // half2, stride 20
    __shared__ __align__(16) unsigned Bs2[64][20];
    const int n0 = blockIdx.x * 64;
    const int m0 = blockIdx.y * 64;
    const int tid = threadIdx.x;
    const int lane = tid & 31, wid = tid >> 5;
    const int wm = wid >> 2, wn = wid & 3;
    const int g = lane >> 2, tg = lane & 3;

    float acc[2][2][4] = {};

    for (int k0 = 0; k0 < DD; k0 += 32) {
#pragma unroll
        for (int i = 0; i < 2; i++) {
            int f = tid + i * 256;
            int r = f >> 3, kq = (f & 7) << 2, k2 = (f & 7) << 1;
            float4 v = *(const float4*)(x + (size_t)(m0 + r) * DD + k0 + kq);
            As2[r][k2] = f2h2(v.x, v.y);
            As2[r][k2 + 1] = f2h2(v.z, v.w);
            float4 w = *(const float4*)(Wi + (size_t)(n0 + r) * DD + k0 + kq);
            Bs2[r][k2] = f2h2(w.x, w.y);
            Bs2[r][k2 + 1] = f2h2(w.z, w.w);
        }
        __syncthreads();

#pragma unroll
        for (int kk2 = 0; kk2 < 16; kk2 += 8) {
            unsigned a[2][4], bf[2][2];
#pragma unroll
            for (int mi = 0; mi < 2; mi++) {
                int r = wm * 32 + mi * 16;
                a[mi][0] = As2[r + g][kk2 + tg];
                a[mi][1] = As2[r + g + 8][kk2 + tg];
                a[mi][2] = As2[r + g][kk2 + tg + 4];
                a[mi][3] = As2[r + g + 8][kk2 + tg + 4];
            }
#pragma unroll
            for (int ni = 0; ni < 2; ni++) {
                int c = wn * 16 + ni * 8;
                bf[ni][0] = Bs2[c + g][kk2 + tg];
                bf[ni][1] = Bs2[c + g][kk2 + tg + 4];
            }
#pragma unroll
            for (int mi = 0; mi < 2; mi++)
#pragma unroll
                for (int ni = 0; ni < 2; ni++)
                    mma_f16(acc[mi][ni], a[mi], bf[ni]);
        }
        __syncthreads();
    }

#pragma unroll
    for (int mi = 0; mi < 2; mi++)
#pragma unroll
        for (int ni = 0; ni < 2; ni++) {
            int row = m0 + wm * 32 + mi * 16 + g;
            int col = n0 + wn * 16 + ni * 8 + 2 * tg;
            float2 bv = *(const float2*)(bi + col);
            *(float2*)(g_xi + (size_t)row * GG + col) =
                make_float2(acc[mi][ni][0] + bv.x, acc[mi][ni][1] + bv.y);
            *(float2*)(g_xi + (size_t)(row + 8) * GG + col) =
                make_float2(acc[mi][ni][2] + bv.x, acc[mi][ni][3] + bv.y);
        }
}

// ---------------------------------------------------------------------------
// Persistent recurrence. grid=128 x 512thr (16 warps = 4/SMSP), 1 CTA/SM.
// 16 warps = 2 m-halves x 8 k-slices (K=128 each). Per warp per step:
// 16 LDG.128 (A) + 16 LDS.128 (B) + 64 HMMA.16816.
// Reduction: 4 Ps arrays; ks<4 write, ks>=4 add; gates sum the 4 arrays.
// Barrier: v4b's proven atomicAdd + epoch publish + relaxed single-word poll.
// ---------------------------------------------------------------------------
__global__ __launch_bounds__(512, 1) void lstm_persist(
    const float* __restrict__ Wh, const float* __restrict__ bh,
    const int* __restrict__ tok, const float* __restrict__ c0,
    float* __restrict__ out, int ne)
{
    extern __shared__ __align__(16) unsigned Bsf[];  // 16384 words = 64 KB
    __shared__ float Ps[4][64][33];                  // 33.8 KB

    const int bid = blockIdx.x;
    const int jb = bid * 8;
    const int tid = threadIdx.x, lane = tid & 31, wid = tid >> 5;
    const int ks = wid >> 1, wmh = wid & 1;          // k-slice (0..7), m-half
    const int g = lane >> 2, tg = lane & 3;

    // One-time: Wh -> fp16 fragment-ready smem.
    // [u(64)][ntp(2)][lane(32)][4 words]; same mapping as v4b.
#pragma unroll
    for (int i = 0; i < 32; i++) {
        int idx = tid + i * 512;                     // 0..16383
        int u = idx >> 8, rest = idx & 255;
        int ntp = rest >> 7, rr = rest & 127;
        int ln = rr >> 2, w = rr & 3;
        int nt = ntp * 2 + (w >> 1), breg = w & 1;
        int gg = ln >> 2, tt = ln & 3;
        int k = u * 16 + 2 * tt + 8 * breg;
        const float* src = Wh + ((size_t)nt * HH + jb + gg) * HH + k;
        float2 v = *(const float2*)src;
        Bsf[idx] = f2h2(v.x, v.y);
    }

    // Gate-phase mapping: 1 output per thread: b = tid>>3, j = tid&7.
    const int b = tid >> 3, j = tid & 7;
    const int col = jb + j;
    float bhv[4];
#pragma unroll
    for (int gate = 0; gate < 4; gate++) bhv[gate] = bh[gate * HH + col];
    float creg = c0[(size_t)b * HH + col];
    float hreg = 0.f;

    // h-store byte offset in the g_h fragment image (2-byte store).
    unsigned hbyte;
    {
        int u = col >> 4, kin = col & 15;
        int mb = b >> 4, r = b & 15;
        int ln = (r & 7) * 4 + ((kin >> 1) & 3);
        int frag = ((kin >> 3) << 1) | (r >> 3);
        unsigned word = ((unsigned)(mb << 6 | u) << 7) + ln * 4 + frag;
        hbyte = word * 4 + (kin & 1) * 2;
    }
    __syncthreads();

    // Loop-carried xi prefetch for step 0.
    float xr[4];
    {
        const float* xb = g_xi + (size_t)b * GG + col;
#pragma unroll
        for (int gate = 0; gate < 4; gate++) xr[gate] = __ldcg(xb + gate * HH);
    }

    for (int t = 0; t < TT; t++) {
        // GEMM: preact[64x32] = h[t-1] @ WhTile^T, K=1024, slice ks (K=128).
        const unsigned* gh = g_h[t & 1];
        const uint4* a0p = (const uint4*)gh + ((2 * wmh + 0) * 64 + ks * 8) * 32 + lane;
        const uint4* a1p = (const uint4*)gh + ((2 * wmh + 1) * 64 + ks * 8) * 32 + lane;
        const uint4* bpp = (const uint4*)Bsf + (ks * 8) * 64 + lane;

        float acc[2][4][4] = {};
#pragma unroll
        for (int uu = 0; uu < 8; uu++) {
            uint4 A0 = __ldcg(a0p + uu * 32);
            uint4 A1 = __ldcg(a1p + uu * 32);
            uint4 B0 = bpp[uu * 64];
            uint4 B1 = bpp[uu * 64 + 32];
            unsigned af0[4] = { A0.x, A0.y, A0.z, A0.w };
            unsigned af1[4] = { A1.x, A1.y, A1.z, A1.w };
            unsigned b0[2] = { B0.x, B0.y }, b1[2] = { B0.z, B0.w };
            unsigned b2[2] = { B1.x, B1.y }, b3[2] = { B1.z, B1.w };
            mma_f16(acc[0][0], af0, b0); mma_f16(acc[0][1], af0, b1);
            mma_f16(acc[0][2], af0, b2); mma_f16(acc[0][3], af0, b3);
            mma_f16(acc[1][0], af1, b0); mma_f16(acc[1][1], af1, b1);
            mma_f16(acc[1][2], af1, b2); mma_f16(acc[1][3], af1, b3);
        }

        // Reduction: ks<4 write Ps[ks]; ks>=4 add into Ps[ks-4].
        if (ks < 4) {
            float (*P)[33] = Ps[ks];
#pragma unroll
            for (int mbi = 0; mbi < 2; mbi++)
#pragma unroll
                for (int nt = 0; nt < 4; nt++) {
                    int r = (2 * wmh + mbi) * 16 + g;
                    int c = nt * 8 + 2 * tg;
                    P[r][c]         = acc[mbi][nt][0];
                    P[r][c + 1]     = acc[mbi][nt][1];
                    P[r + 8][c]     = acc[mbi][nt][2];
                    P[r + 8][c + 1] = acc[mbi][nt][3];
                }
        }
        __syncthreads();
        if (ks >= 4) {
            float (*P)[33] = Ps[ks - 4];
#pragma unroll
            for (int mbi = 0; mbi < 2; mbi++)
#pragma unroll
                for (int nt = 0; nt < 4; nt++) {
                    int r = (2 * wmh + mbi) * 16 + g;
                    int c = nt * 8 + 2 * tg;
                    P[r][c]         += acc[mbi][nt][0];
                    P[r][c + 1]     += acc[mbi][nt][1];
                    P[r + 8][c]     += acc[mbi][nt][2];
                    P[r + 8][c + 1] += acc[mbi][nt][3];
                }
        }
        __syncthreads();

        // Gate phase: one output (b, col) per thread.
        {
            float kc = (t >= 2 && __ldg(tok + (t - 1) * BB + b) == 0) ? 0.f : 1.f;
            float pre[4];
#pragma unroll
            for (int gate = 0; gate < 4; gate++) {
                int c = gate * 8 + j;
                pre[gate] = Ps[0][b][c] + Ps[1][b][c] + Ps[2][b][c] + Ps[3][b][c]
                          + xr[gate] + bhv[gate];
            }
            float iv = sigmf(pre[0]);
            float fv = sigmf(pre[1]);
            float ov = sigmf(pre[2]);
            float gv = tanhx(pre[3]);
            float cn = fv * creg * kc + iv * gv;
            float hn = ov * tanhx(cn);
            creg = cn; hreg = hn;
            float kn = ((t + 1) >= 2 && __ldg(tok + t * BB + b) == 0) ? 0.f : 1.f;
            *(__half*)((char*)g_h[(t + 1) & 1] + hbyte) = __float2half(hn * kn);
            out[(size_t)t * BH + (size_t)b * HH + col] = hn;
        }

        // Grid barrier (v4b-proven): atomicAdd + epoch publish + relaxed poll.
        __syncthreads();
        if (tid == 0) {
            __threadfence();
            unsigned old = atomicAdd(&g_cnt, 1u);
            if (old == (unsigned)(t + 1) * GRID - 1u) {
                __threadfence();
                atomicExch(&g_epoch, (unsigned)(t + 1));
            }
        }
        // Prefetch xi for t+1 while the barrier settles.
        if (t + 1 < TT) {
            const float* xb = g_xi + ((size_t)(t + 1) * BB + b) * GG + col;
#pragma unroll
            for (int gate = 0; gate < 4; gate++) xr[gate] = __ldcg(xb + gate * HH);
        }
        if (tid == 0) {
            unsigned e;
            do {
                asm volatile("ld.global.relaxed.gpu.b32 %0, [%1];"
                             : "=r"(e) : "l"(&g_epoch));
            } while (e < (unsigned)(t + 1));
            __threadfence();
        }
        __syncthreads();
    }

    // hT / cT tail from registers.
    {
        size_t off = (size_t)b * HH + col;
        if (ne >= 1) out[TBH + off] = hreg;
        if (ne >= 2) out[TBH + BH + off] = creg;
    }
}

extern "C" void kernel_launch(void* const* d_in, const int* in_sizes, int n_in,
                              void* d_out, int out_size) {
    const float* x  = (const float*)d_in[0];
    const float* h0 = (const float*)d_in[1];
    const float* c0 = (const float*)d_in[2];
    const float* Wi = (const float*)d_in[3];
    const float* bi = (const float*)d_in[4];
    const float* Wh = (const float*)d_in[5];
    const float* bh = (const float*)d_in[6];
    const int* tok  = (const int*)d_in[7];
    float* out = (float*)d_out;

    const int dyn_smem = 16384 * 4;  // 64 KB
    cudaFuncSetAttribute(lstm_persist, cudaFuncAttributeMaxDynamicSharedMemorySize, dyn_smem);

    init_kernel<<<(4 * 64 * 128 + 255) / 256, 256>>>(h0);
    xi_gemm<<<dim3(GG / 64, (TT * BB) / 64), 256>>>(x, Wi, bi);

    long long extra = ((long long)out_size - (long long)TBH) / BH;
    int ne = extra < 0 ? 0 : (extra > 2 ? 2 : (int)extra);

    lstm_persist<<<GRID, 512, dyn_smem>>>(Wh, bh, tok, c0, out, ne);
}

// round 14
// speedup vs baseline: 1.5722x; 1.1493x over previous
#include <cuda_runtime.h>
#include <cuda_fp16.h>
#include <cstdint>

// AWD-LSTM persistent kernel v8: v7 + single-phase reduction (8 Ps arrays),
// barrier reorder (out/xi after arrival), f16-accumulate HMMA with chunked
// f32 spill. T=1024, B=64, DIN=512, H=1024.
// Inputs: x[T,B,DIN], h0[B,H], c0[B,H], Wi[4H,DIN], bi[4H], Wh[4H,H], bh[4H],
//         input_tokens[T,B] i32.  Output: [ out(T*B*H) | hT(B*H) | cT(B*H) ].

#define TT 1024
#define BB 64
#define DD 512
#define HH 1024
#define GG 4096
#define GRID 128
#define BH   (BB * HH)
#define TBH  ((size_t)TT * BB * HH)
#define PSTR 40                                    // Ps row stride (floats)

// g_h: fp16, A-fragment layout for m16n8k16 (see v4b comment).
__device__ float    g_xi[(size_t)TT * BB * GG];   // 1.07 GB scratch
__device__ unsigned g_h[2][4 * 64 * 128];         // 2 x 128 KB
__device__ unsigned g_cnt;
__device__ unsigned g_epoch;

__device__ __forceinline__ unsigned f2h2(float x, float y) {
    unsigned r;
    asm("cvt.rn.f16x2.f32 %0, %1, %2;" : "=r"(r) : "f"(y), "f"(x));
    return r;
}

__device__ __forceinline__ float2 h22f2(unsigned u) {
    __half2 h = *(__half2*)&u;
    return __half22float2(h);
}

// f32-accumulate (xi GEMM)
__device__ __forceinline__ void mma_f16(float d[4], const unsigned a[4], const unsigned b[2]) {
    asm volatile(
        "mma.sync.aligned.m16n8k16.row.col.f32.f16.f16.f32 "
        "{%0,%1,%2,%3}, {%4,%5,%6,%7}, {%8,%9}, {%0,%1,%2,%3};\n"
        : "+f"(d[0]), "+f"(d[1]), "+f"(d[2]), "+f"(d[3])
        : "r"(a[0]), "r"(a[1]), "r"(a[2]), "r"(a[3]), "r"(b[0]), "r"(b[1]));
}

// f16-accumulate (recurrent GEMM): d0 = (g,2tg|2tg+1), d1 = (g+8,2tg|2tg+1).
__device__ __forceinline__ void mma_f16h(unsigned d[2], const unsigned a[4], const unsigned b[2]) {
    asm volatile(
        "mma.sync.aligned.m16n8k16.row.col.f16.f16.f16.f16 "
        "{%0,%1}, {%2,%3,%4,%5}, {%6,%7}, {%0,%1};\n"
        : "+r"(d[0]), "+r"(d[1])
        : "r"(a[0]), "r"(a[1]), "r"(a[2]), "r"(a[3]), "r"(b[0]), "r"(b[1]));
}

__device__ __forceinline__ float sigmf(float x) {
    return __fdividef(1.f, 1.f + __expf(-x));
}
__device__ __forceinline__ float tanhx(float x) {
    return 2.f * sigmf(2.f * x) - 1.f;
}

// ---------------------------------------------------------------------------
// init: g_h[0] = fp16(h0) in fragment layout; reset barrier state.
// ---------------------------------------------------------------------------
__global__ void init_kernel(const float* __restrict__ h0) {
    int w = blockIdx.x * 256 + threadIdx.x;        // word index, 32768 total
    if (w < 4 * 64 * 128) {
        int mb = w >> 13, u = (w >> 7) & 63;
        int lane = (w >> 2) & 31, frag = w & 3;
        int r = ((frag & 1) << 3) | (lane >> 2);
        int kin = ((frag >> 1) << 3) | ((lane & 3) << 1);
        int b = mb * 16 + r, col = u * 16 + kin;
        float2 v = *(const float2*)(h0 + (size_t)b * HH + col);
        g_h[0][w] = f2h2(v.x, v.y);
    }
    if (blockIdx.x == 0 && threadIdx.x == 0) { g_cnt = 0; g_epoch = 0; }
}

// ---------------------------------------------------------------------------
// xi = x @ Wi^T + bi, fp16 m16n8k16 (f32 acc). M=65536, K=512, N=4096.
// ---------------------------------------------------------------------------
__global__ __launch_bounds__(256) void xi_gemm(const float* __restrict__ x,
                                               const float* __restrict__ Wi,
                                               const float* __restrict__ bi) {
    __shared__ __align__(16) unsigned As2[64][20];   // half2, stride 20
    __shared__ __align__(16) unsigned Bs2[64][20];
    const int n0 = blockIdx.x * 64;
    const int m0 = blockIdx.y * 64;
    const int tid = threadIdx.x;
    const int lane = tid & 31, wid = tid >> 5;
    const int wm = wid >> 2, wn = wid & 3;
    const int g = lane >> 2, tg = lane & 3;

    float acc[2][2][4] = {};

    for (int k0 = 0; k0 < DD; k0 += 32) {
#pragma unroll
        for (int i = 0; i < 2; i++) {
            int f = tid + i * 256;
            int r = f >> 3, kq = (f & 7) << 2, k2 = (f & 7) << 1;
            float4 v = *(const float4*)(x + (size_t)(m0 + r) * DD + k0 + kq);
            As2[r][k2] = f2h2(v.x, v.y);
            As2[r][k2 + 1] = f2h2(v.z, v.w);
            float4 w = *(const float4*)(Wi + (size_t)(n0 + r) * DD + k0 + kq);
            Bs2[r][k2] = f2h2(w.x, w.y);
            Bs2[r][k2 + 1] = f2h2(w.z, w.w);
        }
        __syncthreads();

#pragma unroll
        for (int kk2 = 0; kk2 < 16; kk2 += 8) {
            unsigned a[2][4], bf[2][2];
#pragma unroll
            for (int mi = 0; mi < 2; mi++) {
                int r = wm * 32 + mi * 16;
                a[mi][0] = As2[r + g][kk2 + tg];
                a[mi][1] = As2[r + g + 8][kk2 + tg];
                a[mi][2] = As2[r + g][kk2 + tg + 4];
                a[mi][3] = As2[r + g + 8][kk2 + tg + 4];
            }
#pragma unroll
            for (int ni = 0; ni < 2; ni++) {
                int c = wn * 16 + ni * 8;
                bf[ni][0] = Bs2[c + g][kk2 + tg];
                bf[ni][1] = Bs2[c + g][kk2 + tg + 4];
            }
#pragma unroll
            for (int mi = 0; mi < 2; mi++)
#pragma unroll
                for (int ni = 0; ni < 2; ni++)
                    mma_f16(acc[mi][ni], a[mi], bf[ni]);
        }
        __syncthreads();
    }

#pragma unroll
    for (int mi = 0; mi < 2; mi++)
#pragma unroll
        for (int ni = 0; ni < 2; ni++) {
            int row = m0 + wm * 32 + mi * 16 + g;
            int col = n0 + wn * 16 + ni * 8 + 2 * tg;
            float2 bv = *(const float2*)(bi + col);
            *(float2*)(g_xi + (size_t)row * GG + col) =
                make_float2(acc[mi][ni][0] + bv.x, acc[mi][ni][1] + bv.y);
            *(float2*)(g_xi + (size_t)(row + 8) * GG + col) =
                make_float2(acc[mi][ni][2] + bv.x, acc[mi][ni][3] + bv.y);
        }
}

// ---------------------------------------------------------------------------
// Persistent recurrence. grid=128 x 512thr (16 warps = 4/SMSP), 1 CTA/SM.
// 16 warps = 2 m-halves x 8 k-slices (K=128 each). f16-acc HMMA with f32
// spill every 4 k-iters. Single-phase reduction: warp-pair (ks) writes its
// own Ps[ks]; gate phase sums the 8 arrays (stride 40 -> conflict-free).
// 3 __syncthreads per step. out store + xi prefetch after barrier arrival.
// ---------------------------------------------------------------------------
__global__ __launch_bounds__(512, 1) void lstm_persist(
    const float* __restrict__ Wh, const float* __restrict__ bh,
    const int* __restrict__ tok, const float* __restrict__ c0,
    float* __restrict__ out, int ne)
{
    extern __shared__ __align__(16) unsigned smem_dyn[];
    unsigned* Bsf = smem_dyn;                        // 16384 words = 64 KB
    float* Psf = (float*)(smem_dyn + 16384);         // 8 * 64 * PSTR floats = 80 KB

    const int bid = blockIdx.x;
    const int jb = bid * 8;
    const int tid = threadIdx.x, lane = tid & 31, wid = tid >> 5;
    const int ks = wid >> 1, wmh = wid & 1;          // k-slice (0..7), m-half
    const int g = lane >> 2, tg = lane & 3;

    // One-time: Wh -> fp16 fragment-ready smem (v4b mapping).
#pragma unroll
    for (int i = 0; i < 32; i++) {
        int idx = tid + i * 512;                     // 0..16383
        int u = idx >> 8, rest = idx & 255;
        int ntp = rest >> 7, rr = rest & 127;
        int ln = rr >> 2, w = rr & 3;
        int nt = ntp * 2 + (w >> 1), breg = w & 1;
        int gg = ln >> 2, tt = ln & 3;
        int k = u * 16 + 2 * tt + 8 * breg;
        const float* src = Wh + ((size_t)nt * HH + jb + gg) * HH + k;
        float2 v = *(const float2*)src;
        Bsf[idx] = f2h2(v.x, v.y);
    }

    // Gate-phase mapping: 1 output per thread: b = tid>>3, j = tid&7.
    const int b = tid >> 3, j = tid & 7;
    const int col = jb + j;
    float bhv[4];
#pragma unroll
    for (int gate = 0; gate < 4; gate++) bhv[gate] = bh[gate * HH + col];
    float creg = c0[(size_t)b * HH + col];
    float hreg = 0.f;

    // h-store byte offset in the g_h fragment image (2-byte store).
    unsigned hbyte;
    {
        int u = col >> 4, kin = col & 15;
        int mb = b >> 4, r = b & 15;
        int ln = (r & 7) * 4 + ((kin >> 1) & 3);
        int frag = ((kin >> 3) << 1) | (r >> 3);
        unsigned word = ((unsigned)(mb << 6 | u) << 7) + ln * 4 + frag;
        hbyte = word * 4 + (kin & 1) * 2;
    }
    __syncthreads();

    // Loop-carried xi prefetch for step 0.
    float xr[4];
    {
        const float* xb = g_xi + (size_t)b * GG + col;
#pragma unroll
        for (int gate = 0; gate < 4; gate++) xr[gate] = __ldcg(xb + gate * HH);
    }

    for (int t = 0; t < TT; t++) {
        // GEMM: preact[64x32] = h[t-1] @ WhTile^T, K=1024, slice ks (K=128).
        const unsigned* gh = g_h[t & 1];
        const uint4* a0p = (const uint4*)gh + ((2 * wmh + 0) * 64 + ks * 8) * 32 + lane;
        const uint4* a1p = (const uint4*)gh + ((2 * wmh + 1) * 64 + ks * 8) * 32 + lane;
        const uint4* bpp = (const uint4*)Bsf + (ks * 8) * 64 + lane;

        float accf[2][4][4] = {};
        unsigned acch[2][4][2];
#pragma unroll
        for (int uu = 0; uu < 8; uu++) {
            if ((uu & 3) == 0) {
#pragma unroll
                for (int mbi = 0; mbi < 2; mbi++)
#pragma unroll
                    for (int nt = 0; nt < 4; nt++) {
                        acch[mbi][nt][0] = 0u; acch[mbi][nt][1] = 0u;
                    }
            }
            uint4 A0 = __ldcg(a0p + uu * 32);
            uint4 A1 = __ldcg(a1p + uu * 32);
            uint4 B0 = bpp[uu * 64];
            uint4 B1 = bpp[uu * 64 + 32];
            unsigned af0[4] = { A0.x, A0.y, A0.z, A0.w };
            unsigned af1[4] = { A1.x, A1.y, A1.z, A1.w };
            unsigned b0[2] = { B0.x, B0.y }, b1[2] = { B0.z, B0.w };
            unsigned b2[2] = { B1.x, B1.y }, b3[2] = { B1.z, B1.w };
            mma_f16h(acch[0][0], af0, b0); mma_f16h(acch[0][1], af0, b1);
            mma_f16h(acch[0][2], af0, b2); mma_f16h(acch[0][3], af0, b3);
            mma_f16h(acch[1][0], af1, b0); mma_f16h(acch[1][1], af1, b1);
            mma_f16h(acch[1][2], af1, b2); mma_f16h(acch[1][3], af1, b3);
            if ((uu & 3) == 3) {
#pragma unroll
                for (int mbi = 0; mbi < 2; mbi++)
#pragma unroll
                    for (int nt = 0; nt < 4; nt++) {
                        float2 lo = h22f2(acch[mbi][nt][0]);
                        float2 hi = h22f2(acch[mbi][nt][1]);
                        accf[mbi][nt][0] += lo.x; accf[mbi][nt][1] += lo.y;
                        accf[mbi][nt][2] += hi.x; accf[mbi][nt][3] += hi.y;
                    }
            }
        }

        // Single-phase reduction: warp-pair ks owns Ps[ks].
        {
            float* P = Psf + ks * (64 * PSTR);
#pragma unroll
            for (int mbi = 0; mbi < 2; mbi++)
#pragma unroll
                for (int nt = 0; nt < 4; nt++) {
                    int r = (2 * wmh + mbi) * 16 + g;
                    int c = nt * 8 + 2 * tg;
                    *(float2*)(P + r * PSTR + c) =
                        make_float2(accf[mbi][nt][0], accf[mbi][nt][1]);
                    *(float2*)(P + (r + 8) * PSTR + c) =
                        make_float2(accf[mbi][nt][2], accf[mbi][nt][3]);
                }
        }
        __syncthreads();

        // Gate phase: one output (b, col) per thread; sum the 8 Ps arrays.
        {
            float kc = (t >= 2 && __ldg(tok + (t - 1) * BB + b) == 0) ? 0.f : 1.f;
            float pre[4];
#pragma unroll
            for (int gate = 0; gate < 4; gate++) {
                int c = gate * 8 + j;
                const float* P = Psf + b * PSTR + c;
                float s0 = P[0]             + P[64 * PSTR];
                float s1 = P[2 * 64 * PSTR] + P[3 * 64 * PSTR];
                float s2 = P[4 * 64 * PSTR] + P[5 * 64 * PSTR];
                float s3 = P[6 * 64 * PSTR] + P[7 * 64 * PSTR];
                pre[gate] = ((s0 + s1) + (s2 + s3)) + xr[gate] + bhv[gate];
            }
            float iv = sigmf(pre[0]);
            float fv = sigmf(pre[1]);
            float ov = sigmf(pre[2]);
            float gv = tanhx(pre[3]);
            float cn = fv * creg * kc + iv * gv;
            float hn = ov * tanhx(cn);
            float kn = ((t + 1) >= 2 && __ldg(tok + t * BB + b) == 0) ? 0.f : 1.f;
            *(__half*)((char*)g_h[(t + 1) & 1] + hbyte) = __float2half(hn * kn);
            creg = cn; hreg = hn;
        }

        // Barrier arrival immediately after g_h stores.
        __syncthreads();
        if (tid == 0) {
            __threadfence();
            unsigned old = atomicAdd(&g_cnt, 1u);
            if (old == (unsigned)(t + 1) * GRID - 1u) {
                __threadfence();
                atomicExch(&g_epoch, (unsigned)(t + 1));
            }
        }

        // Off-critical-path work while the barrier settles.
        out[(size_t)t * BH + (size_t)b * HH + col] = hreg;
        if (t + 1 < TT) {
            const float* xb = g_xi + ((size_t)(t + 1) * BB + b) * GG + col;
#pragma unroll
            for (int gate = 0; gate < 4; gate++) xr[gate] = __ldcg(xb + gate * HH);
        }

        if (tid == 0) {
            unsigned e;
            do {
                asm volatile("ld.global.relaxed.gpu.b32 %0, [%1];"
                             : "=r"(e) : "l"(&g_epoch));
            } while (e < (unsigned)(t + 1));
            __threadfence();
        }
        __syncthreads();
    }

    // hT / cT tail from registers.
    {
        size_t off = (size_t)b * HH + col;
        if (ne >= 1) out[TBH + off] = hreg;
        if (ne >= 2) out[TBH + BH + off] = creg;
    }
}

extern "C" void kernel_launch(void* const* d_in, const int* in_sizes, int n_in,
                              void* d_out, int out_size) {
    const float* x  = (const float*)d_in[0];
    const float* h0 = (const float*)d_in[1];
    const float* c0 = (const float*)d_in[2];
    const float* Wi = (const float*)d_in[3];
    const float* bi = (const float*)d_in[4];
    const float* Wh = (const float*)d_in[5];
    const float* bh = (const float*)d_in[6];
    const int* tok  = (const int*)d_in[7];
    float* out = (float*)d_out;

    const int dyn_smem = 16384 * 4 + 8 * 64 * PSTR * 4;  // 64 KB + 80 KB
    cudaFuncSetAttribute(lstm_persist, cudaFuncAttributeMaxDynamicSharedMemorySize, dyn_smem);

    init_kernel<<<(4 * 64 * 128 + 255) / 256, 256>>>(h0);
    xi_gemm<<<dim3(GG / 64, (TT * BB) / 64), 256>>>(x, Wi, bi);

    long long extra = ((long long)out_size - (long long)TBH) / BH;
    int ne = extra < 0 ? 0 : (extra > 2 ? 2 : (int)extra);

    lstm_persist<<<GRID, 512, dyn_smem>>>(Wh, bh, tok, c0, out, ne);
}

// round 16
// speedup vs baseline: 1.6643x; 1.0586x over previous
#include <cuda_runtime.h>
#include <cuda_fp16.h>
#include <cstdint>

// AWD-LSTM persistent kernel v9: M-split partition (grid = 2 batch-halves x
// 64 col-groups) halves the per-step A broadcast; 16 k-slice warps (K=64),
// pure f16-acc HMMA (no spill), f16x2 reduction arrays, conflict-free
// stride-36 Ps layout. T=1024, B=64, DIN=512, H=1024.
// Inputs: x[T,B,DIN], h0[B,H], c0[B,H], Wi[4H,DIN], bi[4H], Wh[4H,H], bh[4H],
//         input_tokens[T,B] i32.  Output: [ out(T*B*H) | hT(B*H) | cT(B*H) ].

#define TT 1024
#define BB 64
#define DD 512
#define HH 1024
#define GG 4096
#define GRID 128
#define BH   (BB * HH)
#define TBH  ((size_t)TT * BB * HH)
#define PSTR 36                 // Ps row stride (4B words); banks 4g+tg
#define PSLICE (32 * PSTR)      // words per slice array (1152)

// g_h: fp16, A-fragment layout for m16n8k16 (v4b mapping).
// [buf][mb(4)][u(64)][32 lanes][4 words]; tile (mb,u) = rows [16mb,16mb+16) x
// k [16u,16u+16). Element (r,kin): lane=(r&7)*4+((kin>>1)&3),
// frag=((kin>>3)<<1)|(r>>3), half lo/hi = kin&1.
__device__ float    g_xi[(size_t)TT * BB * GG];   // 1.07 GB scratch
__device__ unsigned g_h[2][4 * 64 * 128];         // 2 x 128 KB
__device__ unsigned g_cnt;
__device__ unsigned g_epoch;

__device__ __forceinline__ unsigned f2h2(float x, float y) {
    unsigned r;
    asm("cvt.rn.f16x2.f32 %0, %1, %2;" : "=r"(r) : "f"(y), "f"(x));
    return r;
}

__device__ __forceinline__ float2 h22f2(unsigned u) {
    __half2 h = *(__half2*)&u;
    return __half22float2(h);
}

// f32-accumulate (xi GEMM)
__device__ __forceinline__ void mma_f16(float d[4], const unsigned a[4], const unsigned b[2]) {
    asm volatile(
        "mma.sync.aligned.m16n8k16.row.col.f32.f16.f16.f32 "
        "{%0,%1,%2,%3}, {%4,%5,%6,%7}, {%8,%9}, {%0,%1,%2,%3};\n"
        : "+f"(d[0]), "+f"(d[1]), "+f"(d[2]), "+f"(d[3])
        : "r"(a[0]), "r"(a[1]), "r"(a[2]), "r"(a[3]), "r"(b[0]), "r"(b[1]));
}

// f16-accumulate: d0 = (row g, cols 2tg..2tg+1), d1 = (row g+8, same cols).
__device__ __forceinline__ void mma_f16h(unsigned d[2], const unsigned a[4], const unsigned b[2]) {
    asm volatile(
        "mma.sync.aligned.m16n8k16.row.col.f16.f16.f16.f16 "
        "{%0,%1}, {%2,%3,%4,%5}, {%6,%7}, {%0,%1};\n"
        : "+r"(d[0]), "+r"(d[1])
        : "r"(a[0]), "r"(a[1]), "r"(a[2]), "r"(a[3]), "r"(b[0]), "r"(b[1]));
}

__device__ __forceinline__ float sigmf(float x) {
    return __fdividef(1.f, 1.f + __expf(-x));
}
__device__ __forceinline__ float tanhx(float x) {
    return 2.f * sigmf(2.f * x) - 1.f;
}

// ---------------------------------------------------------------------------
// init: g_h[0] = fp16(h0) in fragment layout; reset barrier state.
// ---------------------------------------------------------------------------
__global__ void init_kernel(const float* __restrict__ h0) {
    int w = blockIdx.x * 256 + threadIdx.x;        // word index, 32768 total
    if (w < 4 * 64 * 128) {
        int mb = w >> 13, u = (w >> 7) & 63;
        int lane = (w >> 2) & 31, frag = w & 3;
        int r = ((frag & 1) << 3) | (lane >> 2);
        int kin = ((frag >> 1) << 3) | ((lane & 3) << 1);
        int b = mb * 16 + r, col = u * 16 + kin;
        float2 v = *(const float2*)(h0 + (size_t)b * HH + col);
        g_h[0][w] = f2h2(v.x, v.y);
    }
    if (blockIdx.x == 0 && threadIdx.x == 0) { g_cnt = 0; g_epoch = 0; }
}

// ---------------------------------------------------------------------------
// xi = x @ Wi^T + bi, fp16 m16n8k16 (f32 acc). M=65536, K=512, N=4096.
// ---------------------------------------------------------------------------
__global__ __launch_bounds__(256) void xi_gemm(const float* __restrict__ x,
                                               const float* __restrict__ Wi,
                                               const float* __restrict__ bi) {
    __shared__ __align__(16) unsigned As2[64][20];   // half2, stride 20
    __shared__ __align__(16) unsigned Bs2[64][20];
    const int n0 = blockIdx.x * 64;
    const int m0 = blockIdx.y * 64;
    const int tid = threadIdx.x;
    const int lane = tid & 31, wid = tid >> 5;
    const int wm = wid >> 2, wn = wid & 3;
    const int g = lane >> 2, tg = lane & 3;

    float acc[2][2][4] = {};

    for (int k0 = 0; k0 < DD; k0 += 32) {
#pragma unroll
        for (int i = 0; i < 2; i++) {
            int f = tid + i * 256;
            int r = f >> 3, kq = (f & 7) << 2, k2 = (f & 7) << 1;
            float4 v = *(const float4*)(x + (size_t)(m0 + r) * DD + k0 + kq);
            As2[r][k2] = f2h2(v.x, v.y);
            As2[r][k2 + 1] = f2h2(v.z, v.w);
            float4 w = *(const float4*)(Wi + (size_t)(n0 + r) * DD + k0 + kq);
            Bs2[r][k2] = f2h2(w.x, w.y);
            Bs2[r][k2 + 1] = f2h2(w.z, w.w);
        }
        __syncthreads();

#pragma unroll
        for (int kk2 = 0; kk2 < 16; kk2 += 8) {
            unsigned a[2][4], bf[2][2];
#pragma unroll
            for (int mi = 0; mi < 2; mi++) {
                int r = wm * 32 + mi * 16;
                a[mi][0] = As2[r + g][kk2 + tg];
                a[mi][1] = As2[r + g + 8][kk2 + tg];
                a[mi][2] = As2[r + g][kk2 + tg + 4];
                a[mi][3] = As2[r + g + 8][kk2 + tg + 4];
            }
#pragma unroll
            for (int ni = 0; ni < 2; ni++) {
                int c = wn * 16 + ni * 8;
                bf[ni][0] = Bs2[c + g][kk2 + tg];
                bf[ni][1] = Bs2[c + g][kk2 + tg + 4];
            }
#pragma unroll
            for (int mi = 0; mi < 2; mi++)
#pragma unroll
                for (int ni = 0; ni < 2; ni++)
                    mma_f16(acc[mi][ni], a[mi], bf[ni]);
        }
        __syncthreads();
    }

#pragma unroll
    for (int mi = 0; mi < 2; mi++)
#pragma unroll
        for (int ni = 0; ni < 2; ni++) {
            int row = m0 + wm * 32 + mi * 16 + g;
            int col = n0 + wn * 16 + ni * 8 + 2 * tg;
            float2 bv = *(const float2*)(bi + col);
            *(float2*)(g_xi + (size_t)row * GG + col) =
                make_float2(acc[mi][ni][0] + bv.x, acc[mi][ni][1] + bv.y);
            *(float2*)(g_xi + (size_t)(row + 8) * GG + col) =
                make_float2(acc[mi][ni][2] + bv.x, acc[mi][ni][3] + bv.y);
        }
}

// ---------------------------------------------------------------------------
// Persistent recurrence, M-split. grid=128 = mh(2) x cg(64); block 512 thr.
// Block: M=32 rows [32mh..), N=64 cols (gate-remapped n = gate*16+jj,
// jj = 16cg..), K=1024 over 16 k-slice warps (K=64 each).
// Per warp: 8 LDG.128 (A) + 16 LDS.128 (B) + 64 HMMA.16816 (f16 acc).
// B smem: [u(64)][ntp(4)][lane(32)][4 words]; word q: nt=2ntp+(q>>1),
//   breg=q&1, value = Wh_remap[n=nt*8+(lane>>2)][k=16u+2(lane&3)+8breg .. +1].
// Ps: 16 f16x2 arrays, stride 36 -> STS banks 4g+tg (conflict-free) and
//   gate-read banks const+4g+tg (conflict-free with the pair mapping below).
// Gate: 256 threads, each 2 cols: bq = (lane>>2)+8*(wid>>1),
//   jp = (lane&3)+4*(wid&1).
// ---------------------------------------------------------------------------
__global__ __launch_bounds__(512, 1) void lstm_persist(
    const float* __restrict__ Wh, const float* __restrict__ bh,
    const int* __restrict__ tok, const float* __restrict__ c0,
    float* __restrict__ out, int ne)
{
    extern __shared__ __align__(16) unsigned smem_dyn[];
    unsigned* Bsf = smem_dyn;                        // 32768 words = 128 KB
    unsigned* Psf = smem_dyn + 32768;                // 16*PSLICE words = 72 KB

    const int bid = blockIdx.x;
    const int mh = bid >> 6;                         // batch half (0..1)
    const int cg = bid & 63;                         // column group (0..63)
    const int tid = threadIdx.x, lane = tid & 31, wid = tid >> 5;
    const int ks = wid;                              // k-slice (0..15)
    const int g = lane >> 2, tg = lane & 3;

    // One-time: Wh -> fp16 fragment-ready smem (N=64 tile).
#pragma unroll
    for (int i = 0; i < 64; i++) {
        int idx = tid + i * 512;                     // 0..32767
        int u = idx >> 9, rest = idx & 511;
        int ntp = rest >> 7, rr = rest & 127;
        int ln = rr >> 2, q = rr & 3;
        int nt = ntp * 2 + (q >> 1), breg = q & 1;
        int n = nt * 8 + (ln >> 2);
        int grow = (n >> 4) * HH + cg * 16 + (n & 15);
        int k = u * 16 + 2 * (ln & 3) + 8 * breg;
        float2 v = *(const float2*)(Wh + (size_t)grow * HH + k);
        Bsf[idx] = f2h2(v.x, v.y);
    }

    // Gate-phase mapping (threads 0..255 active): 2 cols per thread.
    const bool gateth = (wid < 8);
    const int bq = (lane >> 2) + 8 * (wid >> 1);     // local row 0..31
    const int jp = (lane & 3) + 4 * (wid & 1);       // col pair 0..7
    const int b = mh * 32 + bq;                      // global batch row
    const int colE = cg * 16 + 2 * jp;               // even global column
    float2 bhv[4], creg = make_float2(0.f, 0.f), hreg = make_float2(0.f, 0.f);
    unsigned hoff = 0;
    if (gateth) {
#pragma unroll
        for (int gate = 0; gate < 4; gate++)
            bhv[gate] = *(const float2*)(bh + gate * HH + colE);
        creg = *(const float2*)(c0 + (size_t)b * HH + colE);
        // h-store: cols colE,colE+1 share one half2 word (u = cg).
        int mb = b >> 4, r = b & 15;
        int ln2 = (r & 7) * 4 + (jp & 3);
        int frag = ((jp >> 2) << 1) | (r >> 3);
        hoff = ((unsigned)(mb << 6 | cg) << 7) + ln2 * 4 + frag;
    }
    __syncthreads();

    // Loop-carried xi prefetch for step 0.
    float2 xr[4];
    if (gateth) {
        const float* xb = g_xi + (size_t)b * GG + colE;
#pragma unroll
        for (int gate = 0; gate < 4; gate++)
            xr[gate] = *(const float2*)(xb + gate * HH);
    }

    for (int t = 0; t < TT; t++) {
        // GEMM: preact[32x64] = h[t-1] @ WhTile^T, K-slice ks (K=64).
        const uint4* ab = (const uint4*)g_h[t & 1];
        unsigned acch[2][8][2] = {};
#pragma unroll
        for (int kk = 0; kk < 4; kk++) {
            int u = 4 * ks + kk;
            uint4 A0 = __ldcg(ab + ((2 * mh + 0) * 64 + u) * 32 + lane);
            uint4 A1 = __ldcg(ab + ((2 * mh + 1) * 64 + u) * 32 + lane);
            const uint4* bp = (const uint4*)Bsf + (u * 4) * 32 + lane;
            uint4 B0 = bp[0];
            uint4 B1 = bp[32];
            uint4 B2 = bp[64];
            uint4 B3 = bp[96];
            unsigned af0[4] = { A0.x, A0.y, A0.z, A0.w };
            unsigned af1[4] = { A1.x, A1.y, A1.z, A1.w };
            unsigned bf[8][2] = {
                { B0.x, B0.y }, { B0.z, B0.w }, { B1.x, B1.y }, { B1.z, B1.w },
                { B2.x, B2.y }, { B2.z, B2.w }, { B3.x, B3.y }, { B3.z, B3.w } };
#pragma unroll
            for (int nt = 0; nt < 8; nt++) {
                mma_f16h(acch[0][nt], af0, bf[nt]);
                mma_f16h(acch[1][nt], af1, bf[nt]);
            }
        }

        // Single-phase reduction: slice ks owns Psf[ks]; raw f16x2 partials.
        {
            unsigned* P = Psf + ks * PSLICE;
#pragma unroll
            for (int mbi = 0; mbi < 2; mbi++)
#pragma unroll
                for (int nt = 0; nt < 8; nt++) {
                    int c2 = nt * 4 + tg;
                    P[(mbi * 16 + g) * PSTR + c2]     = acch[mbi][nt][0];
                    P[(mbi * 16 + g + 8) * PSTR + c2] = acch[mbi][nt][1];
                }
        }
        __syncthreads();

        // Gate phase: threads 0..255, 2 cols each.
        if (gateth) {
            float kc = (t >= 2 && __ldg(tok + (t - 1) * BB + b) == 0) ? 0.f : 1.f;
            float2 pre[4];
#pragma unroll
            for (int gate = 0; gate < 4; gate++) {
                int c2 = gate * 8 + jp;
                const unsigned* P = Psf + bq * PSTR + c2;
                float2 s = make_float2(0.f, 0.f);
#pragma unroll
                for (int sl = 0; sl < 16; sl++) {
                    float2 v = h22f2(P[sl * PSLICE]);
                    s.x += v.x; s.y += v.y;
                }
                pre[gate] = make_float2(s.x + xr[gate].x + bhv[gate].x,
                                        s.y + xr[gate].y + bhv[gate].y);
            }
            float h2[2], c2v[2];
#pragma unroll
            for (int z = 0; z < 2; z++) {
                float pi = z ? pre[0].y : pre[0].x;
                float pf = z ? pre[1].y : pre[1].x;
                float po = z ? pre[2].y : pre[2].x;
                float pg = z ? pre[3].y : pre[3].x;
                float iv = sigmf(pi);
                float fv = sigmf(pf);
                float ov = sigmf(po);
                float gv = tanhx(pg);
                float cold = (z ? creg.y : creg.x) * kc;
                float cn = fv * cold + iv * gv;
                c2v[z] = cn;
                h2[z] = ov * tanhx(cn);
            }
            creg = make_float2(c2v[0], c2v[1]);
            hreg = make_float2(h2[0], h2[1]);
            float kn = ((t + 1) >= 2 && __ldg(tok + t * BB + b) == 0) ? 0.f : 1.f;
            g_h[(t + 1) & 1][hoff] = f2h2(h2[0] * kn, h2[1] * kn);
        }

        // Barrier arrival immediately after g_h stores.
        __syncthreads();
        if (tid == 0) {
            __threadfence();
            unsigned old = atomicAdd(&g_cnt, 1u);
            if (old == (unsigned)(t + 1) * GRID - 1u) {
                __threadfence();
                atomicExch(&g_epoch, (unsigned)(t + 1));
            }
        }

        // Off-critical-path work while the barrier settles.
        if (gateth) {
            *(float2*)(out + (size_t)t * BH + (size_t)b * HH + colE) = hreg;
            if (t + 1 < TT) {
                const float* xb = g_xi + ((size_t)(t + 1) * BB + b) * GG + colE;
#pragma unroll
                for (int gate = 0; gate < 4; gate++)
                    xr[gate] = *(const float2*)(xb + gate * HH);
            }
        }

        if (tid == 0) {
            unsigned e;
            do {
                asm volatile("ld.global.relaxed.gpu.b32 %0, [%1];"
                             : "=r"(e) : "l"(&g_epoch));
            } while (e < (unsigned)(t + 1));
            __threadfence();
        }
        __syncthreads();
    }

    // hT / cT tail from registers.
    if (gateth) {
        size_t off = (size_t)b * HH + colE;
        if (ne >= 1) *(float2*)(out + TBH + off) = hreg;
        if (ne >= 2) *(float2*)(out + TBH + BH + off) = creg;
    }
}

extern "C" void kernel_launch(void* const* d_in, const int* in_sizes, int n_in,
                              void* d_out, int out_size) {
    const float* x  = (const float*)d_in[0];
    const float* h0 = (const float*)d_in[1];
    const float* c0 = (const float*)d_in[2];
    const float* Wi = (const float*)d_in[3];
    const float* bi = (const float*)d_in[4];
    const float* Wh = (const float*)d_in[5];
    const float* bh = (const float*)d_in[6];
    const int* tok  = (const int*)d_in[7];
    float* out = (float*)d_out;

    const int dyn_smem = (32768 + 16 * PSLICE) * 4;  // 128 KB + 72 KB
    cudaFuncSetAttribute(lstm_persist, cudaFuncAttributeMaxDynamicSharedMemorySize, dyn_smem);

    init_kernel<<<(4 * 64 * 128 + 255) / 256, 256>>>(h0);
    xi_gemm<<<dim3(GG / 64, (TT * BB) / 64), 256>>>(x, Wi, bi);

    long long extra = ((long long)out_size - (long long)TBH) / BH;
    int ne = extra < 0 ? 0 : (extra > 2 ? 2 : (int)extra);

    lstm_persist<<<GRID, 512, dyn_smem>>>(Wh, bh, tok, c0, out, ne);
}